// round 3
// baseline (speedup 1.0000x reference)
#include <cuda_runtime.h>
#include <math.h>

// Problem constants
#define BB 16
#define LL 2048
#define DM 512
#define FF 1025       // LL/2 + 1
#define HH 8
#define EE 64
#define OO 512        // HH*EE
#define NFFT 2048

// ---------------- device scratch (static globals; no allocation) ----------------
__device__ float g_tr[(size_t)BB * DM * LL];            // 67 MB transpose scratch
__device__ float g_re[3][(size_t)BB * DM * FF];         // FFT real parts (b,c,f)
__device__ float g_im[3][(size_t)BB * DM * FF];         // FFT imag parts
__device__ float g_head[3][(size_t)BB * FF * OO];       // qh/kh/vh  (b,h,f,e)
__device__ float g_scores[(size_t)BB * HH * FF * FF];   // 538 MB scores/attn scratch
__device__ float g_ctx[(size_t)BB * FF * OO];           // (b,f, h*e)
__device__ float g_yre[(size_t)BB * DM * FF];           // output-proj complex (b,d,f)
__device__ float g_yim[(size_t)BB * DM * FF];
__device__ float g_W0[3][OO * DM];
__device__ float g_W1[3][OO * DM];
__device__ float g_w2[3][OO];

// ---------------- weight prep ----------------
__global__ void prep_w(const float* __restrict__ Wq, const float* __restrict__ Wk,
                       const float* __restrict__ Wv) {
    int idx = blockIdx.x * blockDim.x + threadIdx.x;
    if (idx >= 3 * OO * DM) return;
    int t = idx / (OO * DM);
    int r = idx % (OO * DM);
    const float* W = (t == 0) ? Wq : (t == 1) ? Wk : Wv;
    g_W0[t][r] = W[r * 3 + 0];
    g_W1[t][r] = W[r * 3 + 1];
}

__global__ void prep_w2(const float* __restrict__ Wq, const float* __restrict__ Wk,
                        const float* __restrict__ Wv) {
    int idx = blockIdx.x * blockDim.x + threadIdx.x;
    if (idx >= 3 * OO) return;
    int t = idx / OO;
    int o = idx % OO;
    const float* W = (t == 0) ? Wq : (t == 1) ? Wk : Wv;
    float s = 0.f;
    for (int c = 0; c < DM; ++c) s += W[(o * DM + c) * 3 + 2];
    g_w2[t][o] = s;
}

// ---------------- transpose (B, Ld, Cd) -> (B, Cd, Ld) ----------------
__global__ void transpose_kernel(const float* __restrict__ in, float* __restrict__ out,
                                 int Ld, int Cd) {
    __shared__ float tile[32][33];
    int b = blockIdx.z;
    int l0 = blockIdx.x * 32, c0 = blockIdx.y * 32;
    int tx = threadIdx.x, ty = threadIdx.y;
    #pragma unroll
    for (int i = 0; i < 32; i += 8) {
        int l = l0 + ty + i, c = c0 + tx;
        if (l < Ld && c < Cd) tile[ty + i][tx] = in[((size_t)b * Ld + l) * Cd + c];
    }
    __syncthreads();
    #pragma unroll
    for (int i = 0; i < 32; i += 8) {
        int c = c0 + ty + i, l = l0 + tx;
        if (c < Cd && l < Ld) out[((size_t)b * Cd + c) * Ld + l] = tile[tx][ty + i];
    }
}

// ---------------- forward rfft: two real channels per complex FFT ----------------
__global__ void rfft_pair(const float* __restrict__ x, int ti) {
    __shared__ float2 s[NFFT];
    int blk = blockIdx.x;
    int b = blk / (DM / 2);
    int p = (blk % (DM / 2)) * 2;
    const float* x0 = x + ((size_t)b * DM + p) * LL;
    int t = threadIdx.x;   // 512 threads
    for (int i = t; i < NFFT; i += 512) {
        int r = __brev((unsigned)i) >> 21;
        s[r] = make_float2(x0[i], x0[i + LL]);
    }
    __syncthreads();
    for (int sh = 0; sh < 11; ++sh) {
        int half = 1 << sh;
        for (int j = t; j < NFFT / 2; j += 512) {
            int pos = j & (half - 1);
            int base = ((j >> sh) << (sh + 1)) | pos;
            float ang = -3.14159265358979f * (float)pos / (float)half;
            float sw, cw; __sincosf(ang, &sw, &cw);
            float2 a = s[base], q2 = s[base + half];
            float tr = cw * q2.x - sw * q2.y;
            float tiy = cw * q2.y + sw * q2.x;
            s[base]        = make_float2(a.x + tr, a.y + tiy);
            s[base + half] = make_float2(a.x - tr, a.y - tiy);
        }
        __syncthreads();
    }
    float* re = g_re[ti];
    float* im = g_im[ti];
    size_t o0 = ((size_t)b * DM + p) * FF;
    for (int f = t; f <= NFFT / 2; f += 512) {
        float2 Zf = s[f];
        float2 Zn = s[(NFFT - f) & (NFFT - 1)];
        re[o0 + f]      = 0.5f * (Zf.x + Zn.x);
        im[o0 + f]      = 0.5f * (Zf.y - Zn.y);
        re[o0 + FF + f] = 0.5f * (Zf.y + Zn.y);
        im[o0 + FF + f] = 0.5f * (Zn.x - Zf.x);
    }
}

// ---------------- projection GEMM: y[b,f,o] = Re·W0 + Im·W1 + freq*w2 + bias ----------------
__global__ void proj_kernel(int ti, const float* __restrict__ bias) {
    __shared__ float Ar[16][68], Ai[16][68], B0[16][68], B1[16][68];
    int b = blockIdx.z;
    int f0 = blockIdx.x * 64;
    int h  = blockIdx.y;
    int tid = threadIdx.x;
    int ty = tid >> 4, tx = tid & 15;
    const float* re = g_re[ti];
    const float* im = g_im[ti];
    const float* W0 = g_W0[ti];
    const float* W1 = g_W1[ti];
    float acc[4][4] = {};
    for (int c0 = 0; c0 < DM; c0 += 16) {
        #pragma unroll
        for (int k = 0; k < 4; ++k) {
            int idx = tid + k * 256;
            int cc = idx >> 6, fi = idx & 63;
            int f = f0 + fi;
            float vr = 0.f, vi = 0.f;
            if (f < FF) {
                size_t ai = ((size_t)b * DM + c0 + cc) * FF + f;
                vr = re[ai]; vi = im[ai];
            }
            Ar[cc][fi] = vr; Ai[cc][fi] = vi;
        }
        #pragma unroll
        for (int k = 0; k < 4; ++k) {
            int idx = tid + k * 256;
            int o = idx >> 4, cc = idx & 15;
            size_t wi = (size_t)(h * 64 + o) * DM + c0 + cc;
            B0[cc][o] = W0[wi];
            B1[cc][o] = W1[wi];
        }
        __syncthreads();
        #pragma unroll
        for (int cc = 0; cc < 16; ++cc) {
            float ar[4], aim[4], b0[4], b1[4];
            #pragma unroll
            for (int i = 0; i < 4; ++i) { ar[i] = Ar[cc][ty * 4 + i]; aim[i] = Ai[cc][ty * 4 + i]; }
            #pragma unroll
            for (int j = 0; j < 4; ++j) { b0[j] = B0[cc][tx * 4 + j]; b1[j] = B1[cc][tx * 4 + j]; }
            #pragma unroll
            for (int i = 0; i < 4; ++i)
                #pragma unroll
                for (int j = 0; j < 4; ++j)
                    acc[i][j] += ar[i] * b0[j] + aim[i] * b1[j];
        }
        __syncthreads();
    }
    const float* w2 = g_w2[ti];
    float* outh = g_head[ti];
    #pragma unroll
    for (int i = 0; i < 4; ++i) {
        int f = f0 + ty * 4 + i;
        if (f >= FF) continue;
        float fr = (float)f / (float)NFFT;
        #pragma unroll
        for (int j = 0; j < 4; ++j) {
            int e = tx * 4 + j;
            int o = h * 64 + e;
            float v2 = acc[i][j] + fr * w2[o] + bias[o];
            outh[(((size_t)b * HH + h) * FF + f) * EE + e] = v2;
        }
    }
}

// ---------------- scores: S = scale * Q K^T per (b,h) ----------------
__global__ void scores_kernel() {
    __shared__ float Qs[64][65], Ks[64][65];
    int bh = blockIdx.z;
    int l0 = blockIdx.x * 64, s0 = blockIdx.y * 64;
    int tid = threadIdx.x;
    int ty = tid >> 4, tx = tid & 15;
    const float* qh = g_head[0];
    const float* kh = g_head[1];
    size_t base = (size_t)bh * FF * EE;
    #pragma unroll
    for (int k = 0; k < 16; ++k) {
        int idx = tid + k * 256;
        int li = idx >> 6, ee = idx & 63;
        int l = l0 + li;
        Qs[li][ee] = (l < FF) ? qh[base + (size_t)l * EE + ee] : 0.f;
        int ss = s0 + li;
        Ks[li][ee] = (ss < FF) ? kh[base + (size_t)ss * EE + ee] : 0.f;
    }
    __syncthreads();
    float acc[4][4] = {};
    #pragma unroll 8
    for (int ee = 0; ee < 64; ++ee) {
        float qr[4], kr[4];
        #pragma unroll
        for (int i = 0; i < 4; ++i) qr[i] = Qs[ty * 4 + i][ee];
        #pragma unroll
        for (int j = 0; j < 4; ++j) kr[j] = Ks[tx * 4 + j][ee];
        #pragma unroll
        for (int i = 0; i < 4; ++i)
            #pragma unroll
            for (int j = 0; j < 4; ++j)
                acc[i][j] += qr[i] * kr[j];
    }
    const float scale = 0.125f;   // 1/sqrt(64)
    #pragma unroll
    for (int i = 0; i < 4; ++i) {
        int l = l0 + ty * 4 + i;
        if (l >= FF) continue;
        #pragma unroll
        for (int j = 0; j < 4; ++j) {
            int ss = s0 + tx * 4 + j;
            if (ss < FF)
                g_scores[((size_t)bh * FF + l) * FF + ss] = acc[i][j] * scale;
        }
    }
}

// ---------------- softmax over last axis (row length FF) ----------------
__global__ void softmax_kernel(const float* __restrict__ S, float* __restrict__ A) {
    __shared__ float red[256];
    size_t row = blockIdx.x;
    const float* p = S + row * FF;
    float* q = A + row * FF;
    int t = threadIdx.x;
    float v[5];
    float mx = -1e30f;
    #pragma unroll
    for (int i = 0; i < 5; ++i) {
        int idx = t + i * 256;
        v[i] = (idx < FF) ? p[idx] : -1e30f;
        mx = fmaxf(mx, v[i]);
    }
    red[t] = mx; __syncthreads();
    for (int s = 128; s > 0; s >>= 1) {
        if (t < s) red[t] = fmaxf(red[t], red[t + s]);
        __syncthreads();
    }
    mx = red[0];
    __syncthreads();
    float sum = 0.f;
    #pragma unroll
    for (int i = 0; i < 5; ++i) {
        v[i] = __expf(v[i] - mx);
        sum += v[i];
    }
    red[t] = sum; __syncthreads();
    for (int s = 128; s > 0; s >>= 1) {
        if (t < s) red[t] += red[t + s];
        __syncthreads();
    }
    float inv = 1.0f / red[0];
    #pragma unroll
    for (int i = 0; i < 5; ++i) {
        int idx = t + i * 256;
        if (idx < FF) q[idx] = v[i] * inv;
    }
}

// ---------------- ctx = attn @ V per (b,h), output (b,f,h,e) ----------------
__global__ void ctx_kernel(const float* __restrict__ A) {
    __shared__ float As[64][17], Vs[16][65];
    int bh = blockIdx.z;
    int b = bh >> 3, h = bh & 7;
    int l0 = blockIdx.x * 64;
    int tid = threadIdx.x;
    int ty = tid >> 4, tx = tid & 15;
    const float* vh = g_head[2];
    size_t arow = (size_t)bh * FF;
    float acc[4][4] = {};
    for (int s0 = 0; s0 < FF; s0 += 16) {
        #pragma unroll
        for (int k = 0; k < 4; ++k) {
            int idx = tid + k * 256;
            int li = idx >> 4, cc = idx & 15;
            int l = l0 + li, ss = s0 + cc;
            As[li][cc] = (l < FF && ss < FF) ? A[(arow + l) * FF + ss] : 0.f;
        }
        #pragma unroll
        for (int k = 0; k < 4; ++k) {
            int idx = tid + k * 256;
            int si = idx >> 6, ee = idx & 63;
            int ss = s0 + si;
            Vs[si][ee] = (ss < FF) ? vh[(arow + ss) * EE + ee] : 0.f;
        }
        __syncthreads();
        #pragma unroll
        for (int cc = 0; cc < 16; ++cc) {
            float ar[4], bv[4];
            #pragma unroll
            for (int i = 0; i < 4; ++i) ar[i] = As[ty * 4 + i][cc];
            #pragma unroll
            for (int j = 0; j < 4; ++j) bv[j] = Vs[cc][tx * 4 + j];
            #pragma unroll
            for (int i = 0; i < 4; ++i)
                #pragma unroll
                for (int j = 0; j < 4; ++j)
                    acc[i][j] += ar[i] * bv[j];
        }
        __syncthreads();
    }
    #pragma unroll
    for (int i = 0; i < 4; ++i) {
        int l = l0 + ty * 4 + i;
        if (l >= FF) continue;
        #pragma unroll
        for (int j = 0; j < 4; ++j) {
            int e = tx * 4 + j;
            g_ctx[(((size_t)b * FF + l) * HH + h) * EE + e] = acc[i][j];
        }
    }
}

// ---------------- output projection: y = ctx @ Wo^T + bo, split to complex (b,d,f) ----------------
__global__ void outproj_kernel(const float* __restrict__ Wo, const float* __restrict__ bo) {
    __shared__ float As[64][17], Bs[64][17];
    const int M = BB * FF;   // 16400
    int m0 = blockIdx.x * 64, j0 = blockIdx.y * 64;
    int tid = threadIdx.x;
    int ty = tid >> 4, tx = tid & 15;
    float acc[4][4] = {};
    for (int c0 = 0; c0 < OO; c0 += 16) {
        #pragma unroll
        for (int k = 0; k < 4; ++k) {
            int idx = tid + k * 256;
            int mi = idx >> 4, cc = idx & 15;
            int m = m0 + mi;
            As[mi][cc] = (m < M) ? g_ctx[(size_t)m * OO + c0 + cc] : 0.f;
            Bs[mi][cc] = Wo[(size_t)(j0 + mi) * OO + c0 + cc];
        }
        __syncthreads();
        #pragma unroll
        for (int cc = 0; cc < 16; ++cc) {
            float ar[4], br[4];
            #pragma unroll
            for (int i = 0; i < 4; ++i) ar[i] = As[ty * 4 + i][cc];
            #pragma unroll
            for (int j = 0; j < 4; ++j) br[j] = Bs[tx * 4 + j][cc];
            #pragma unroll
            for (int i = 0; i < 4; ++i)
                #pragma unroll
                for (int j = 0; j < 4; ++j)
                    acc[i][j] += ar[i] * br[j];
        }
        __syncthreads();
    }
    #pragma unroll
    for (int i = 0; i < 4; ++i) {
        int m = m0 + ty * 4 + i;
        if (m >= M) continue;
        int b = m / FF, f = m % FF;
        #pragma unroll
        for (int j = 0; j < 4; ++j) {
            int jj = j0 + tx * 4 + j;
            float v2 = acc[i][j] + bo[jj];
            int dd = jj >> 1;
            if (jj & 1) g_yim[((size_t)b * DM + dd) * FF + f] = v2;
            else        g_yre[((size_t)b * DM + dd) * FF + f] = v2;
        }
    }
}

// ---------------- inverse rfft: two real outputs per complex iFFT ----------------
// NOTE: jnp.fft.irfft (pocketfft c2r) treats bins 0 and N/2 as purely real —
// their imaginary parts are DISCARDED. We must do the same.
__global__ void irfft_pair(float* __restrict__ xout) {
    __shared__ float2 s[NFFT];
    int blk = blockIdx.x;
    int b = blk / (DM / 2);
    int p = (blk % (DM / 2)) * 2;
    size_t i0 = ((size_t)b * DM + p) * FF;
    int t = threadIdx.x;  // 512
    for (int f = t; f <= NFFT / 2; f += 512) {
        float y0r = g_yre[i0 + f],      y0i = g_yim[i0 + f];
        float y1r = g_yre[i0 + FF + f], y1i = g_yim[i0 + FF + f];
        if (f == 0 || f == NFFT / 2) { y0i = 0.f; y1i = 0.f; }   // irfft semantics
        int r1 = __brev((unsigned)f) >> 21;
        s[r1] = make_float2(y0r - y1i, y0i + y1r);
        if (f > 0 && f < NFFT / 2) {
            int r2 = __brev((unsigned)(NFFT - f)) >> 21;
            s[r2] = make_float2(y0r + y1i, y1r - y0i);
        }
    }
    __syncthreads();
    for (int sh = 0; sh < 11; ++sh) {
        int half = 1 << sh;
        for (int j = t; j < NFFT / 2; j += 512) {
            int pos = j & (half - 1);
            int base = ((j >> sh) << (sh + 1)) | pos;
            float ang = 3.14159265358979f * (float)pos / (float)half;   // inverse sign
            float sw, cw; __sincosf(ang, &sw, &cw);
            float2 a = s[base], q2 = s[base + half];
            float tr = cw * q2.x - sw * q2.y;
            float tiy = cw * q2.y + sw * q2.x;
            s[base]        = make_float2(a.x + tr, a.y + tiy);
            s[base + half] = make_float2(a.x - tr, a.y - tiy);
        }
        __syncthreads();
    }
    const float inv = 1.0f / (float)NFFT;
    size_t o0 = ((size_t)b * DM + p) * LL;
    for (int n = t; n < NFFT; n += 512) {
        xout[o0 + n]      = s[n].x * inv;
        xout[o0 + LL + n] = s[n].y * inv;
    }
}

// ---------------- launch ----------------
extern "C" void kernel_launch(void* const* d_in, const int* in_sizes, int n_in,
                              void* d_out, int out_size) {
    const float* q  = (const float*)d_in[0];
    const float* k  = (const float*)d_in[1];
    const float* v  = (const float*)d_in[2];
    const float* Wq = (const float*)d_in[3];
    const float* bq = (const float*)d_in[4];
    const float* Wk = (const float*)d_in[5];
    const float* bk = (const float*)d_in[6];
    const float* Wv = (const float*)d_in[7];
    const float* bv = (const float*)d_in[8];
    const float* Wo = (const float*)d_in[9];
    const float* bo = (const float*)d_in[10];
    float* out = (float*)d_out;

    const long long OUT_N  = (long long)BB * LL * DM;           // 16,777,216
    const long long ATTN_N = (long long)BB * HH * FF * FF;      // 134,480,000

    float* scores_dev = nullptr;
    cudaGetSymbolAddress((void**)&scores_dev, g_scores);
    float* tr = nullptr;
    cudaGetSymbolAddress((void**)&tr, g_tr);

    // If the harness expects (out, attn) concatenated, export attn into d_out tail.
    float* attn_ptr = scores_dev;
    if ((long long)out_size >= OUT_N + ATTN_N) attn_ptr = out + OUT_N;

    prep_w<<<(3 * OO * DM + 255) / 256, 256>>>(Wq, Wk, Wv);
    prep_w2<<<(3 * OO + 255) / 256, 256>>>(Wq, Wk, Wv);

    dim3 tb(32, 8);
    const float* ins[3]    = {q, k, v};
    const float* biases[3] = {bq, bk, bv};
    for (int ti = 0; ti < 3; ++ti) {
        dim3 tg(LL / 32, DM / 32, BB);
        transpose_kernel<<<tg, tb>>>(ins[ti], tr, LL, DM);
        rfft_pair<<<BB * DM / 2, 512>>>(tr, ti);
        dim3 pg(17, HH, BB);
        proj_kernel<<<pg, 256>>>(ti, biases[ti]);
    }

    dim3 sg(17, 17, BB * HH);
    scores_kernel<<<sg, 256>>>();

    softmax_kernel<<<BB * HH * FF, 256>>>(scores_dev, attn_ptr);

    dim3 cg(17, 1, BB * HH);
    ctx_kernel<<<cg, 256>>>(attn_ptr);

    dim3 og((BB * FF + 63) / 64, 16);
    outproj_kernel<<<og, 256>>>(Wo, bo);

    irfft_pair<<<BB * DM / 2, 512>>>(tr);

    dim3 tg2(DM / 32, LL / 32, BB);
    transpose_kernel<<<tg2, tb>>>(tr, out, DM, LL);
}

// round 5
// speedup vs baseline: 1.6308x; 1.6308x over previous
#include <cuda_runtime.h>
#include <math.h>

// Problem constants
#define BB 16
#define LL 2048
#define DM 512
#define FF 1025       // LL/2 + 1
#define FFP 1152      // padded F (9 tiles of 128); pads stay zero (zero-init, never written)
#define HH 8
#define EE 64
#define OO 512        // HH*EE
#define NFFT 2048
#define KP 1024       // proj interleaved K = 2*DM

// ---------------- device scratch (static globals; zero-initialized) ----------------
__device__ float g_tr[(size_t)BB * DM * LL];                  // transpose scratch
__device__ float g_spec[3][(size_t)BB * KP * FFP];            // interleaved re/im rows (b, 2c+p, f)
__device__ float g_Wt[3][(size_t)KP * OO];                    // interleaved weights [k][o]
__device__ float g_w2[3][OO];
__device__ float g_qkT[2][(size_t)BB * OO * FFP];             // q,k heads (b, o, f)  [e-major rows]
__device__ float g_v[(size_t)BB * HH * FFP * EE];             // v heads (b,h,f,e)
__device__ float g_ctx[(size_t)BB * FFP * OO];                // (b, f, h*e)
__device__ float g_scores[(size_t)BB * HH * FF * FF];         // attn fallback
__device__ float g_yre[(size_t)BB * DM * FF];
__device__ float g_yim[(size_t)BB * DM * FF];

// ---------------- f32x2 packed helpers ----------------
__device__ __forceinline__ unsigned long long pk2(float x, float y) {
    unsigned long long r;
    asm("mov.b64 %0, {%1, %2};" : "=l"(r) : "f"(x), "f"(y));
    return r;
}
__device__ __forceinline__ void fma2(unsigned long long& d, unsigned long long a,
                                     unsigned long long b) {
    asm("fma.rn.f32x2 %0, %1, %2, %0;" : "+l"(d) : "l"(a), "l"(b));
}
__device__ __forceinline__ void upk2(unsigned long long v, float& x, float& y) {
    asm("mov.b64 {%0, %1}, %2;" : "=f"(x), "=f"(y) : "l"(v));
}

// ---------------- weight prep: interleave W0/W1 rows ----------------
__global__ void prep_w(const float* __restrict__ Wq, const float* __restrict__ Wk,
                       const float* __restrict__ Wv) {
    int idx = blockIdx.x * blockDim.x + threadIdx.x;
    if (idx >= 3 * KP * OO) return;
    int t = idx / (KP * OO);
    int r = idx % (KP * OO);
    int k = r / OO, o = r % OO;
    const float* W = (t == 0) ? Wq : (t == 1) ? Wk : Wv;
    g_Wt[t][(size_t)k * OO + o] = W[(o * DM + (k >> 1)) * 3 + (k & 1)];
}

__global__ void prep_w2(const float* __restrict__ Wq, const float* __restrict__ Wk,
                        const float* __restrict__ Wv) {
    int idx = blockIdx.x * blockDim.x + threadIdx.x;
    if (idx >= 3 * OO) return;
    int t = idx / OO;
    int o = idx % OO;
    const float* W = (t == 0) ? Wq : (t == 1) ? Wk : Wv;
    float s = 0.f;
    for (int c = 0; c < DM; ++c) s += W[(o * DM + c) * 3 + 2];
    g_w2[t][o] = s;
}

// ---------------- transpose (B, Ld, Cd) -> (B, Cd, Ld) ----------------
__global__ void transpose_kernel(const float* __restrict__ in, float* __restrict__ out,
                                 int Ld, int Cd) {
    __shared__ float tile[32][33];
    int b = blockIdx.z;
    int l0 = blockIdx.x * 32, c0 = blockIdx.y * 32;
    int tx = threadIdx.x, ty = threadIdx.y;
    #pragma unroll
    for (int i = 0; i < 32; i += 8) {
        int l = l0 + ty + i, c = c0 + tx;
        if (l < Ld && c < Cd) tile[ty + i][tx] = in[((size_t)b * Ld + l) * Cd + c];
    }
    __syncthreads();
    #pragma unroll
    for (int i = 0; i < 32; i += 8) {
        int c = c0 + ty + i, l = l0 + tx;
        if (c < Cd && l < Ld) out[((size_t)b * Cd + c) * Ld + l] = tile[tx][ty + i];
    }
}

// ---------------- forward rfft: two real channels per complex FFT ----------------
__global__ void rfft_pair(const float* __restrict__ x, int ti) {
    __shared__ float2 s[NFFT];
    int blk = blockIdx.x;
    int b = blk / (DM / 2);
    int p = (blk % (DM / 2)) * 2;
    const float* x0 = x + ((size_t)b * DM + p) * LL;
    int t = threadIdx.x;   // 512 threads
    for (int i = t; i < NFFT; i += 512) {
        int r = __brev((unsigned)i) >> 21;
        s[r] = make_float2(x0[i], x0[i + LL]);
    }
    __syncthreads();
    for (int sh = 0; sh < 11; ++sh) {
        int half = 1 << sh;
        for (int j = t; j < NFFT / 2; j += 512) {
            int pos = j & (half - 1);
            int base = ((j >> sh) << (sh + 1)) | pos;
            float ang = -3.14159265358979f * (float)pos / (float)half;
            float sw, cw; __sincosf(ang, &sw, &cw);
            float2 a = s[base], q2 = s[base + half];
            float tr = cw * q2.x - sw * q2.y;
            float tiy = cw * q2.y + sw * q2.x;
            s[base]        = make_float2(a.x + tr, a.y + tiy);
            s[base + half] = make_float2(a.x - tr, a.y - tiy);
        }
        __syncthreads();
    }
    float* sp = g_spec[ti];
    size_t o0 = ((size_t)b * KP + 2 * p) * FFP;
    for (int f = t; f <= NFFT / 2; f += 512) {
        float2 Zf = s[f];
        float2 Zn = s[(NFFT - f) & (NFFT - 1)];
        sp[o0 + f]            = 0.5f * (Zf.x + Zn.x);   // re ch p
        sp[o0 + FFP + f]      = 0.5f * (Zf.y - Zn.y);   // im ch p
        sp[o0 + 2 * FFP + f]  = 0.5f * (Zf.y + Zn.y);   // re ch p+1
        sp[o0 + 3 * FFP + f]  = 0.5f * (Zn.x - Zf.x);   // im ch p+1
    }
}

// ============ common 128x128 f32x2 inner product (16 k-steps) ============
#define GEMM_INNER_128(As, Bs, acc, ty, tx)                                          \
    _Pragma("unroll")                                                                \
    for (int kk = 0; kk < 16; ++kk) {                                                \
        float4 a0 = *(const float4*)&As[kk][(ty) * 4];                               \
        float4 a1 = *(const float4*)&As[kk][64 + (ty) * 4];                          \
        float4 b0 = *(const float4*)&Bs[kk][(tx) * 4];                               \
        float4 b1 = *(const float4*)&Bs[kk][64 + (tx) * 4];                          \
        unsigned long long bb0 = pk2(b0.x, b0.y), bb1 = pk2(b0.z, b0.w);             \
        unsigned long long bb2 = pk2(b1.x, b1.y), bb3 = pk2(b1.z, b1.w);             \
        float av[8] = {a0.x, a0.y, a0.z, a0.w, a1.x, a1.y, a1.z, a1.w};              \
        _Pragma("unroll")                                                            \
        for (int r = 0; r < 8; ++r) {                                                \
            unsigned long long ad = pk2(av[r], av[r]);                               \
            fma2(acc[r][0], ad, bb0); fma2(acc[r][1], ad, bb1);                      \
            fma2(acc[r][2], ad, bb2); fma2(acc[r][3], ad, bb3);                      \
        }                                                                            \
    }

// ---------------- projection GEMM: y[b,f,o] = sum_k spec[k,f]*Wt[k,o] + freq*w2 + bias ----------------
__global__ __launch_bounds__(256, 2) void proj_kernel(int ti, const float* __restrict__ bias) {
    __shared__ float As[16][132], Bs[16][132];
    int b = blockIdx.z;
    int f0 = blockIdx.x * 128;
    int n0 = blockIdx.y * 128;
    int tid = threadIdx.x, ty = tid >> 4, tx = tid & 15;
    const float* sp = g_spec[ti];
    const float* Wt = g_Wt[ti];
    unsigned long long acc[8][4];
    #pragma unroll
    for (int r = 0; r < 8; ++r)
        #pragma unroll
        for (int c = 0; c < 4; ++c) acc[r][c] = 0ull;

    for (int k0 = 0; k0 < KP; k0 += 16) {
        #pragma unroll
        for (int r = 0; r < 2; ++r) {
            int idx = tid + r * 256;
            int kk = idx >> 5, pos = (idx & 31) * 4;
            *(float4*)&As[kk][pos] =
                *(const float4*)&sp[((size_t)b * KP + k0 + kk) * FFP + f0 + pos];
            *(float4*)&Bs[kk][pos] =
                *(const float4*)&Wt[(size_t)(k0 + kk) * OO + n0 + pos];
        }
        __syncthreads();
        GEMM_INNER_128(As, Bs, acc, ty, tx);
        __syncthreads();
    }

    float C[8][8];
    #pragma unroll
    for (int r = 0; r < 8; ++r)
        #pragma unroll
        for (int p2 = 0; p2 < 4; ++p2) upk2(acc[r][p2], C[r][p2 * 2], C[r][p2 * 2 + 1]);

    const float* w2 = g_w2[ti];
    #pragma unroll
    for (int r = 0; r < 8; ++r) {
        int f = f0 + ((r < 4) ? ty * 4 + r : 64 + ty * 4 + (r - 4));
        if (f >= FF) continue;
        float fr = (float)f * (1.0f / (float)NFFT);
        #pragma unroll
        for (int c = 0; c < 8; ++c) {
            int o = n0 + ((c < 4) ? tx * 4 + c : 64 + tx * 4 + (c - 4));
            float val = C[r][c] + fr * w2[o] + bias[o];
            if (ti < 2) {
                g_qkT[ti][((size_t)b * OO + o) * FFP + f] = val;
            } else {
                int h = o >> 6, e = o & 63;
                g_v[(((size_t)b * HH + h) * FFP + f) * EE + e] = val;
            }
        }
    }
}

// ---------------- scores: S = scale * Q K^T per (b,h), scalar stores (FF row stride!) ----------------
__global__ __launch_bounds__(256, 2) void scores_kernel(float* __restrict__ attn) {
    __shared__ float As[16][132], Bs[16][132];
    int bh = blockIdx.z;
    int l0 = blockIdx.x * 128, s0 = blockIdx.y * 128;
    int tid = threadIdx.x, ty = tid >> 4, tx = tid & 15;
    const float* qb = g_qkT[0] + (size_t)bh * EE * FFP;
    const float* kb = g_qkT[1] + (size_t)bh * EE * FFP;
    unsigned long long acc[8][4];
    #pragma unroll
    for (int r = 0; r < 8; ++r)
        #pragma unroll
        for (int c = 0; c < 4; ++c) acc[r][c] = 0ull;

    for (int k0 = 0; k0 < EE; k0 += 16) {
        #pragma unroll
        for (int r = 0; r < 2; ++r) {
            int idx = tid + r * 256;
            int kk = idx >> 5, pos = (idx & 31) * 4;
            *(float4*)&As[kk][pos] = *(const float4*)&qb[(size_t)(k0 + kk) * FFP + l0 + pos];
            *(float4*)&Bs[kk][pos] = *(const float4*)&kb[(size_t)(k0 + kk) * FFP + s0 + pos];
        }
        __syncthreads();
        GEMM_INNER_128(As, Bs, acc, ty, tx);
        __syncthreads();
    }

    float C[8][8];
    #pragma unroll
    for (int r = 0; r < 8; ++r)
        #pragma unroll
        for (int p2 = 0; p2 < 4; ++p2) upk2(acc[r][p2], C[r][p2 * 2], C[r][p2 * 2 + 1]);

    const float scale = 0.125f;   // 1/sqrt(64)
    // Row stride FF=1025 is odd -> NO vector stores (misaligned-trap); scalar STG only.
    #pragma unroll
    for (int r = 0; r < 8; ++r) {
        int l = l0 + ((r < 4) ? ty * 4 + r : 64 + ty * 4 + (r - 4));
        if (l >= FF) continue;
        size_t row = ((size_t)bh * FF + l) * FF;
        #pragma unroll
        for (int c = 0; c < 8; ++c) {
            int s = s0 + ((c < 4) ? tx * 4 + c : 64 + tx * 4 + (c - 4));
            if (s < FF) attn[row + s] = C[r][c] * scale;
        }
    }
}

// ---------------- softmax over last axis, in place ----------------
__global__ void softmax_kernel(float* __restrict__ A) {
    __shared__ float red[256];
    size_t row = blockIdx.x;
    float* p = A + row * FF;
    int t = threadIdx.x;
    float v[5];
    float mx = -1e30f;
    #pragma unroll
    for (int i = 0; i < 5; ++i) {
        int idx = t + i * 256;
        v[i] = (idx < FF) ? p[idx] : -1e30f;
        mx = fmaxf(mx, v[i]);
    }
    red[t] = mx; __syncthreads();
    for (int s = 128; s > 0; s >>= 1) {
        if (t < s) red[t] = fmaxf(red[t], red[t + s]);
        __syncthreads();
    }
    mx = red[0];
    __syncthreads();
    float sum = 0.f;
    #pragma unroll
    for (int i = 0; i < 5; ++i) {
        v[i] = __expf(v[i] - mx);
        sum += v[i];
    }
    red[t] = sum; __syncthreads();
    for (int s = 128; s > 0; s >>= 1) {
        if (t < s) red[t] += red[t + s];
        __syncthreads();
    }
    float inv = 1.0f / red[0];
    #pragma unroll
    for (int i = 0; i < 5; ++i) {
        int idx = t + i * 256;
        if (idx < FF) p[idx] = v[i] * inv;
    }
}

// ---------------- ctx = attn @ V per (b,h); 128x64 tile, 8x4 per thread ----------------
__global__ __launch_bounds__(256, 2) void ctx_kernel(const float* __restrict__ attn) {
    __shared__ float As[16][132], Bs[16][68];
    int bh = blockIdx.z;
    int l0 = blockIdx.x * 128;
    int tid = threadIdx.x, ty = tid >> 4, tx = tid & 15;
    const float* vb = g_v + (size_t)bh * FFP * EE;
    const float* Ab = attn + (size_t)bh * FF * FF;
    unsigned long long acc[8][2];
    #pragma unroll
    for (int r = 0; r < 8; ++r) { acc[r][0] = 0ull; acc[r][1] = 0ull; }

    for (int s0 = 0; s0 < 1040; s0 += 16) {
        // A tile: transpose-load attn[l][s] -> As[s][l], guarded, scalar loads
        #pragma unroll
        for (int r = 0; r < 8; ++r) {
            int idx = tid + r * 256;
            int li = idx >> 4, ss = idx & 15;
            int l = l0 + li, s = s0 + ss;
            As[ss][li] = (l < FF && s < FF) ? Ab[(size_t)l * FF + s] : 0.f;
        }
        // B tile: vh rows direct
        {
            int kk = tid >> 4, pos = (tid & 15) * 4;
            *(float4*)&Bs[kk][pos] = *(const float4*)&vb[(size_t)(s0 + kk) * EE + pos];
        }
        __syncthreads();
        #pragma unroll
        for (int kk = 0; kk < 16; ++kk) {
            float4 a0 = *(const float4*)&As[kk][ty * 4];
            float4 a1 = *(const float4*)&As[kk][64 + ty * 4];
            float4 b0 = *(const float4*)&Bs[kk][tx * 4];
            unsigned long long bb0 = pk2(b0.x, b0.y), bb1 = pk2(b0.z, b0.w);
            float av[8] = {a0.x, a0.y, a0.z, a0.w, a1.x, a1.y, a1.z, a1.w};
            #pragma unroll
            for (int r = 0; r < 8; ++r) {
                unsigned long long ad = pk2(av[r], av[r]);
                fma2(acc[r][0], ad, bb0);
                fma2(acc[r][1], ad, bb1);
            }
        }
        __syncthreads();
    }

    int b = bh >> 3, h = bh & 7;
    #pragma unroll
    for (int r = 0; r < 8; ++r) {
        int l = l0 + ((r < 4) ? ty * 4 + r : 64 + ty * 4 + (r - 4));
        if (l >= FF) continue;
        float c0, c1, c2, c3;
        upk2(acc[r][0], c0, c1);
        upk2(acc[r][1], c2, c3);
        *(float4*)&g_ctx[((size_t)b * FFP + l) * OO + h * EE + tx * 4] =
            make_float4(c0, c1, c2, c3);
    }
}

// ---------------- output projection: y = ctx @ Wo^T + bo, split to complex (b,d,f) ----------------
__global__ __launch_bounds__(256, 2) void outproj_kernel(const float* __restrict__ Wo,
                                                         const float* __restrict__ bo) {
    __shared__ float As[16][132], Bs[16][132];
    int b = blockIdx.z;
    int m0 = blockIdx.x * 128;   // f tile
    int n0 = blockIdx.y * 128;   // output col tile (of 1024)
    int tid = threadIdx.x, ty = tid >> 4, tx = tid & 15;
    unsigned long long acc[8][4];
    #pragma unroll
    for (int r = 0; r < 8; ++r)
        #pragma unroll
        for (int c = 0; c < 4; ++c) acc[r][c] = 0ull;

    for (int c0 = 0; c0 < OO; c0 += 16) {
        int mi = tid >> 1, cg = (tid & 1) * 8;
        // A transpose-load: ctx[(b,f)][c] -> As[c][f]
        {
            const float* src = &g_ctx[((size_t)b * FFP + m0 + mi) * OO + c0 + cg];
            float4 t0 = *(const float4*)&src[0];
            float4 t1 = *(const float4*)&src[4];
            As[cg + 0][mi] = t0.x; As[cg + 1][mi] = t0.y;
            As[cg + 2][mi] = t0.z; As[cg + 3][mi] = t0.w;
            As[cg + 4][mi] = t1.x; As[cg + 5][mi] = t1.y;
            As[cg + 6][mi] = t1.z; As[cg + 7][mi] = t1.w;
        }
        // B transpose-load: Wo[j][c] -> Bs[c][j]
        {
            const float* src = &Wo[(size_t)(n0 + mi) * OO + c0 + cg];
            float4 t0 = *(const float4*)&src[0];
            float4 t1 = *(const float4*)&src[4];
            Bs[cg + 0][mi] = t0.x; Bs[cg + 1][mi] = t0.y;
            Bs[cg + 2][mi] = t0.z; Bs[cg + 3][mi] = t0.w;
            Bs[cg + 4][mi] = t1.x; Bs[cg + 5][mi] = t1.y;
            Bs[cg + 6][mi] = t1.z; Bs[cg + 7][mi] = t1.w;
        }
        __syncthreads();
        GEMM_INNER_128(As, Bs, acc, ty, tx);
        __syncthreads();
    }

    float C[8][8];
    #pragma unroll
    for (int r = 0; r < 8; ++r)
        #pragma unroll
        for (int p2 = 0; p2 < 4; ++p2) upk2(acc[r][p2], C[r][p2 * 2], C[r][p2 * 2 + 1]);

    #pragma unroll
    for (int r = 0; r < 8; ++r) {
        int f = m0 + ((r < 4) ? ty * 4 + r : 64 + ty * 4 + (r - 4));
        if (f >= FF) continue;
        #pragma unroll
        for (int c = 0; c < 8; ++c) {
            int jj = n0 + ((c < 4) ? tx * 4 + c : 64 + tx * 4 + (c - 4));
            float val = C[r][c] + bo[jj];
            int dd = jj >> 1;
            if (jj & 1) g_yim[((size_t)b * DM + dd) * FF + f] = val;
            else        g_yre[((size_t)b * DM + dd) * FF + f] = val;
        }
    }
}

// ---------------- inverse rfft (irfft discards imag of bins 0 and N/2) ----------------
__global__ void irfft_pair(float* __restrict__ xout) {
    __shared__ float2 s[NFFT];
    int blk = blockIdx.x;
    int b = blk / (DM / 2);
    int p = (blk % (DM / 2)) * 2;
    size_t i0 = ((size_t)b * DM + p) * FF;
    int t = threadIdx.x;  // 512
    for (int f = t; f <= NFFT / 2; f += 512) {
        float y0r = g_yre[i0 + f],      y0i = g_yim[i0 + f];
        float y1r = g_yre[i0 + FF + f], y1i = g_yim[i0 + FF + f];
        if (f == 0 || f == NFFT / 2) { y0i = 0.f; y1i = 0.f; }
        int r1 = __brev((unsigned)f) >> 21;
        s[r1] = make_float2(y0r - y1i, y0i + y1r);
        if (f > 0 && f < NFFT / 2) {
            int r2 = __brev((unsigned)(NFFT - f)) >> 21;
            s[r2] = make_float2(y0r + y1i, y1r - y0i);
        }
    }
    __syncthreads();
    for (int sh = 0; sh < 11; ++sh) {
        int half = 1 << sh;
        for (int j = t; j < NFFT / 2; j += 512) {
            int pos = j & (half - 1);
            int base = ((j >> sh) << (sh + 1)) | pos;
            float ang = 3.14159265358979f * (float)pos / (float)half;
            float sw, cw; __sincosf(ang, &sw, &cw);
            float2 a = s[base], q2 = s[base + half];
            float tr = cw * q2.x - sw * q2.y;
            float tiy = cw * q2.y + sw * q2.x;
            s[base]        = make_float2(a.x + tr, a.y + tiy);
            s[base + half] = make_float2(a.x - tr, a.y - tiy);
        }
        __syncthreads();
    }
    const float inv = 1.0f / (float)NFFT;
    size_t o0 = ((size_t)b * DM + p) * LL;
    for (int n = t; n < NFFT; n += 512) {
        xout[o0 + n]      = s[n].x * inv;
        xout[o0 + LL + n] = s[n].y * inv;
    }
}

// ---------------- launch ----------------
extern "C" void kernel_launch(void* const* d_in, const int* in_sizes, int n_in,
                              void* d_out, int out_size) {
    const float* q  = (const float*)d_in[0];
    const float* k  = (const float*)d_in[1];
    const float* v  = (const float*)d_in[2];
    const float* Wq = (const float*)d_in[3];
    const float* bq = (const float*)d_in[4];
    const float* Wk = (const float*)d_in[5];
    const float* bk = (const float*)d_in[6];
    const float* Wv = (const float*)d_in[7];
    const float* bv = (const float*)d_in[8];
    const float* Wo = (const float*)d_in[9];
    const float* bo = (const float*)d_in[10];
    float* out = (float*)d_out;

    const long long OUT_N  = (long long)BB * LL * DM;           // 16,777,216
    const long long ATTN_N = (long long)BB * HH * FF * FF;      // 134,480,000

    float* scores_dev = nullptr;
    cudaGetSymbolAddress((void**)&scores_dev, g_scores);
    float* tr = nullptr;
    cudaGetSymbolAddress((void**)&tr, g_tr);

    float* attn_ptr = scores_dev;
    if ((long long)out_size >= OUT_N + ATTN_N) attn_ptr = out + OUT_N;

    prep_w<<<(3 * KP * OO + 255) / 256, 256>>>(Wq, Wk, Wv);
    prep_w2<<<(3 * OO + 255) / 256, 256>>>(Wq, Wk, Wv);

    dim3 tb(32, 8);
    const float* ins[3]    = {q, k, v};
    const float* biases[3] = {bq, bk, bv};
    for (int ti = 0; ti < 3; ++ti) {
        dim3 tg(LL / 32, DM / 32, BB);
        transpose_kernel<<<tg, tb>>>(ins[ti], tr, LL, DM);
        rfft_pair<<<BB * DM / 2, 512>>>(tr, ti);
        dim3 pg(FFP / 128, OO / 128, BB);
        proj_kernel<<<pg, 256>>>(ti, biases[ti]);
    }

    dim3 sg(FFP / 128, FFP / 128, BB * HH);
    scores_kernel<<<sg, 256>>>(attn_ptr);

    softmax_kernel<<<BB * HH * FF, 256>>>(attn_ptr);

    dim3 cg(FFP / 128, 1, BB * HH);
    ctx_kernel<<<cg, 256>>>(attn_ptr);

    dim3 og(FFP / 128, 8, BB);
    outproj_kernel<<<og, 256>>>(Wo, bo);

    irfft_pair<<<BB * DM / 2, 512>>>(tr);

    dim3 tg2(DM / 32, LL / 32, BB);
    transpose_kernel<<<tg2, tb>>>(tr, out, DM, LL);
}